// round 1
// baseline (speedup 1.0000x reference)
#include <cuda_runtime.h>
#include <cstdint>

#define KDIM 256
#define BM 128
#define BN 256
#define BK 16
#define SA 20    // A smem row stride (floats) — frag loads conflict-free
#define SB 264   // B smem row stride (floats) — frag loads conflict-free

__device__ __forceinline__ float tf32_rna(float x) {
    float y;
    asm("cvt.rna.tf32.f32 %0, %1;" : "=f"(y) : "f"(x));
    return y;
}

__device__ __forceinline__ void mma_tf32(float* d,
    uint32_t a0, uint32_t a1, uint32_t a2, uint32_t a3,
    uint32_t b0, uint32_t b1) {
    asm volatile(
        "mma.sync.aligned.m16n8k8.row.col.f32.tf32.tf32.f32 "
        "{%0,%1,%2,%3}, {%4,%5,%6,%7}, {%8,%9}, {%0,%1,%2,%3};"
        : "+f"(d[0]), "+f"(d[1]), "+f"(d[2]), "+f"(d[3])
        : "r"(a0), "r"(a1), "r"(a2), "r"(a3), "r"(b0), "r"(b1));
}

__global__ __launch_bounds__(512, 1)
void cp2d_tf32_kernel(const float* __restrict__ x,
                      const float* __restrict__ W,
                      float* __restrict__ out) {
    __shared__ float As[BM * SA];
    __shared__ float Bs[BK * SB];

    const int tid  = threadIdx.x;
    const int lane = tid & 31;
    const int warp = tid >> 5;
    const int g    = lane >> 2;    // groupID (0..7)
    const int tig  = lane & 3;     // thread-in-group (0..3)
    const int wm   = warp & 3;     // 4 warps along M (32 rows each)
    const int wn   = warp >> 2;    // 4 warps along N (64 cols each)
    const long m0  = (long)blockIdx.x * BM;

    float acc[2][8][4];
#pragma unroll
    for (int mt = 0; mt < 2; mt++)
#pragma unroll
        for (int nt = 0; nt < 8; nt++)
#pragma unroll
            for (int i = 0; i < 4; i++) acc[mt][nt][i] = 0.f;

    // A tile: 128 rows x 16 floats = 512 float4, 1 per thread
    const int arow = tid >> 2;
    const int ac   = (tid & 3) * 4;
    // B tile: 16 rows x 256 floats = 1024 float4, 2 per thread
    const int br0  = tid >> 6;        // rows 0..7
    const int br1  = br0 + 8;         // rows 8..15
    const int bc   = (tid & 63) * 4;

    for (int k0 = 0; k0 < KDIM; k0 += BK) {
        // issue global loads first (overlap with barrier drain)
        float4 av  = *(const float4*)(x + (m0 + arow) * KDIM + k0 + ac);
        float4 bv0 = *(const float4*)(W + (long)(k0 + br0) * KDIM + bc);
        float4 bv1 = *(const float4*)(W + (long)(k0 + br1) * KDIM + bc);

        __syncthreads();   // previous iteration's smem reads done

        As[arow * SA + ac + 0] = tf32_rna(av.x);
        As[arow * SA + ac + 1] = tf32_rna(av.y);
        As[arow * SA + ac + 2] = tf32_rna(av.z);
        As[arow * SA + ac + 3] = tf32_rna(av.w);

        Bs[br0 * SB + bc + 0] = tf32_rna(bv0.x);
        Bs[br0 * SB + bc + 1] = tf32_rna(bv0.y);
        Bs[br0 * SB + bc + 2] = tf32_rna(bv0.z);
        Bs[br0 * SB + bc + 3] = tf32_rna(bv0.w);

        Bs[br1 * SB + bc + 0] = tf32_rna(bv1.x);
        Bs[br1 * SB + bc + 1] = tf32_rna(bv1.y);
        Bs[br1 * SB + bc + 2] = tf32_rna(bv1.z);
        Bs[br1 * SB + bc + 3] = tf32_rna(bv1.w);

        __syncthreads();

#pragma unroll
        for (int ks = 0; ks < 2; ks++) {
            const int kk = ks * 8;
            uint32_t af[2][4];
#pragma unroll
            for (int mt = 0; mt < 2; mt++) {
                const int r = wm * 32 + mt * 16;
                af[mt][0] = __float_as_uint(As[(r + g    ) * SA + kk + tig    ]);
                af[mt][1] = __float_as_uint(As[(r + g + 8) * SA + kk + tig    ]);
                af[mt][2] = __float_as_uint(As[(r + g    ) * SA + kk + tig + 4]);
                af[mt][3] = __float_as_uint(As[(r + g + 8) * SA + kk + tig + 4]);
            }
#pragma unroll
            for (int nt = 0; nt < 8; nt++) {
                const int c = wn * 64 + nt * 8 + g;
                uint32_t b0 = __float_as_uint(Bs[(kk + tig    ) * SB + c]);
                uint32_t b1 = __float_as_uint(Bs[(kk + tig + 4) * SB + c]);
                mma_tf32(acc[0][nt], af[0][0], af[0][1], af[0][2], af[0][3], b0, b1);
                mma_tf32(acc[1][nt], af[1][0], af[1][1], af[1][2], af[1][3], b0, b1);
            }
        }
    }

    // epilogue: each mma tile writes 2x (float2 per row)
#pragma unroll
    for (int mt = 0; mt < 2; mt++) {
        const long r0 = m0 + wm * 32 + mt * 16 + g;
#pragma unroll
        for (int nt = 0; nt < 8; nt++) {
            const int c = wn * 64 + nt * 8 + tig * 2;
            *(float2*)(out + r0 * KDIM + c) =
                make_float2(acc[mt][nt][0], acc[mt][nt][1]);
            *(float2*)(out + (r0 + 8) * KDIM + c) =
                make_float2(acc[mt][nt][2], acc[mt][nt][3]);
        }
    }
}

extern "C" void kernel_launch(void* const* d_in, const int* in_sizes, int n_in,
                              void* d_out, int out_size) {
    const float* x = (const float*)d_in[0];
    const float* W = (const float*)d_in[1];
    float* out = (float*)d_out;

    const int M = in_sizes[0] / KDIM;     // 401408
    dim3 grid(M / BM);                    // 3136 blocks (M divisible by 128)
    cp2d_tf32_kernel<<<grid, 512>>>(x, W, out);
}

// round 3
// speedup vs baseline: 2.2711x; 2.2711x over previous
#include <cuda_runtime.h>
#include <cuda_fp16.h>
#include <cstdint>

#define KDIM   256
#define BM     128
#define BN     256
#define BK     64
#define NCHUNK 4

#define A_STAGE_BYTES (BM * BK * 2)       // 16384
#define B_STAGE_BYTES (BN * BK * 2)       // 32768
#define STAGE_BYTES   (A_STAGE_BYTES + B_STAGE_BYTES)  // 49152
#define SMEM_TOTAL    (2 * STAGE_BYTES)   // 98304

// W^T in fp16: g_Wt[n][k] = half(W[k][n])
__device__ __align__(256) __half g_Wt[KDIM * KDIM];

// ---------------- helpers ----------------
__device__ __forceinline__ uint32_t smem_u32(const void* p) {
    uint32_t a;
    asm("{ .reg .u64 t; cvta.to.shared.u64 t, %1; cvt.u32.u64 %0, t; }" : "=r"(a) : "l"(p));
    return a;
}
__device__ __forceinline__ void cp16(uint32_t dst, const void* src) {
    asm volatile("cp.async.cg.shared.global [%0], [%1], 16;" :: "r"(dst), "l"(src));
}
__device__ __forceinline__ void cp_commit() {
    asm volatile("cp.async.commit_group;" ::: "memory");
}
template <int N> __device__ __forceinline__ void cp_wait() {
    asm volatile("cp.async.wait_group %0;" :: "n"(N) : "memory");
}
#define LDSM4(r0, r1, r2, r3, a)                                              \
    asm volatile("ldmatrix.sync.aligned.m8n8.x4.shared.b16 {%0,%1,%2,%3}, [%4];" \
                 : "=r"(r0), "=r"(r1), "=r"(r2), "=r"(r3) : "r"(a))

__device__ __forceinline__ void mma_fp16(float* d, const uint32_t* a,
                                         uint32_t b0, uint32_t b1) {
    asm volatile(
        "mma.sync.aligned.m16n8k16.row.col.f32.f16.f16.f32 "
        "{%0,%1,%2,%3}, {%4,%5,%6,%7}, {%8,%9}, {%0,%1,%2,%3};"
        : "+f"(d[0]), "+f"(d[1]), "+f"(d[2]), "+f"(d[3])
        : "r"(a[0]), "r"(a[1]), "r"(a[2]), "r"(a[3]), "r"(b0), "r"(b1));
}

// ---------------- prep: W[K,N] fp32 -> Wt[N,K] fp16 ----------------
__global__ void prep_wt_kernel(const float* __restrict__ W) {
    int n = blockIdx.x, k = threadIdx.x;
    g_Wt[n * KDIM + k] = __float2half_rn(W[k * KDIM + n]);
}

// ---------------- main GEMM ----------------
__global__ __launch_bounds__(512, 1)
void cp2d_fp16_kernel(const float* __restrict__ x, float* __restrict__ out) {
    extern __shared__ __align__(128) char smem[];
    const uint32_t sb = smem_u32(smem);

    const int tid  = threadIdx.x;
    const int lane = tid & 31;
    const int warp = tid >> 5;
    const int wm   = warp & 3;          // 4 warps along M
    const int wn   = warp >> 2;         // 4 warps along N
    const long m0  = (long)blockIdx.x * BM;

    // A global-load / STS mapping: 128 rows x 16 float4 per chunk, 4/thread
    const int a_f   = tid & 15;         // float4 index along k (covers k = a_f*4..+3)
    const int a_row = tid >> 4;         // base row (0..31), rows row + j*32
    // B cp.async mapping: 256 rows x 8 x 16B per chunk, 4/thread
    const int b_u   = tid & 7;          // 16B unit along k
    const int b_row = tid >> 3;         // base row (0..63), rows row + j*64

    // ldmatrix per-lane invariants
    const int la_row = (lane & 7) + ((lane >> 3) & 1) * 8;   // A: 0..15
    const int la_u   = lane >> 4;                            // A: +0/+1 unit
    const int lb_row = (lane & 7) + ((lane >> 4) & 1) * 8;   // B: 0..15
    const int lb_u   = (lane >> 3) & 1;                      // B: +0/+1 unit

    float acc[2][8][4];
#pragma unroll
    for (int mt = 0; mt < 2; mt++)
#pragma unroll
        for (int nt = 0; nt < 8; nt++)
#pragma unroll
            for (int i = 0; i < 4; i++) acc[mt][nt][i] = 0.f;

    float4 rA[4];

    auto ldgA = [&](int c) {
#pragma unroll
        for (int j = 0; j < 4; j++)
            rA[j] = *(const float4*)(x + (m0 + a_row + j * 32) * KDIM + c * BK + a_f * 4);
    };
    auto stsA = [&](int st) {
        const uint32_t aBase = sb + st * STAGE_BYTES;
        const int u = a_f >> 1, off8 = (a_f & 1) * 8;
#pragma unroll
        for (int j = 0; j < 4; j++) {
            const int row = a_row + j * 32;
            uint32_t addr = aBase + row * 128 + ((u ^ (row & 7)) << 4) + off8;
            __half2 h0 = __floats2half2_rn(rA[j].x, rA[j].y);
            __half2 h1 = __floats2half2_rn(rA[j].z, rA[j].w);
            asm volatile("st.shared.v2.b32 [%0], {%1, %2};"
                         :: "r"(addr), "r"(*(uint32_t*)&h0), "r"(*(uint32_t*)&h1));
        }
    };
    auto cpB = [&](int c, int st) {
        const uint32_t bBase = sb + st * STAGE_BYTES + A_STAGE_BYTES;
#pragma unroll
        for (int j = 0; j < 4; j++) {
            const int row = b_row + j * 64;
            uint32_t dst = bBase + row * 128 + (((b_u) ^ (row & 7)) << 4);
            cp16(dst, g_Wt + row * KDIM + c * BK + b_u * 8);
        }
        cp_commit();
    };

    auto compute = [&](int st) {
        const uint32_t aBase = sb + st * STAGE_BYTES;
        const uint32_t bBase = aBase + A_STAGE_BYTES;
#pragma unroll
        for (int ks = 0; ks < 4; ks++) {
            const int u0 = ks * 2;
            uint32_t a[2][4];
#pragma unroll
            for (int mt = 0; mt < 2; mt++) {
                const int row = wm * 32 + mt * 16 + la_row;
                uint32_t addr = aBase + row * 128 + (((u0 + la_u) ^ (row & 7)) << 4);
                LDSM4(a[mt][0], a[mt][1], a[mt][2], a[mt][3], addr);
            }
            uint32_t b[4][4];
#pragma unroll
            for (int nt2 = 0; nt2 < 4; nt2++) {
                const int row = wn * 64 + nt2 * 16 + lb_row;
                uint32_t addr = bBase + row * 128 + (((u0 + lb_u) ^ (row & 7)) << 4);
                LDSM4(b[nt2][0], b[nt2][1], b[nt2][2], b[nt2][3], addr);
            }
#pragma unroll
            for (int nt2 = 0; nt2 < 4; nt2++)
#pragma unroll
                for (int s = 0; s < 2; s++) {
                    const int nt = nt2 * 2 + s;
                    mma_fp16(acc[0][nt], a[0], b[nt2][2 * s], b[nt2][2 * s + 1]);
                    mma_fp16(acc[1][nt], a[1], b[nt2][2 * s], b[nt2][2 * s + 1]);
                }
        }
    };

    // ---- prologue ----
    ldgA(0);
    cpB(0, 0);
    stsA(0);
    ldgA(1);
    cpB(1, 1);
    cp_wait<1>();
    __syncthreads();        // stage 0 fully ready

    // ---- main loop ----
#pragma unroll
    for (int c = 0; c < NCHUNK; c++) {
        const int st = c & 1;
        compute(st);
        if (c == NCHUNK - 1) break;
        __syncthreads();    // all warps done reading stage st
        stsA(st ^ 1);       // A chunk c+1 -> other stage
        if (c + 2 < NCHUNK) {
            ldgA(c + 2);
            cpB(c + 2, st); // B chunk c+2 -> this stage (now free)
        }
        if (c < NCHUNK - 2) cp_wait<1>(); else cp_wait<0>();
        __syncthreads();    // stage st^1 fully ready
    }

    // ---- epilogue: direct STG from accumulators ----
    const int er = lane >> 2;            // 0..7
    const int ec = (lane & 3) * 2;       // 0,2,4,6
#pragma unroll
    for (int mt = 0; mt < 2; mt++) {
        const long r0 = m0 + wm * 32 + mt * 16 + er;
#pragma unroll
        for (int nt = 0; nt < 8; nt++) {
            const int col = wn * 64 + nt * 8 + ec;
            *(float2*)(out + r0 * KDIM + col) =
                make_float2(acc[mt][nt][0], acc[mt][nt][1]);
            *(float2*)(out + (r0 + 8) * KDIM + col) =
                make_float2(acc[mt][nt][2], acc[mt][nt][3]);
        }
    }
}

extern "C" void kernel_launch(void* const* d_in, const int* in_sizes, int n_in,
                              void* d_out, int out_size) {
    const float* x = (const float*)d_in[0];
    const float* W = (const float*)d_in[1];
    float* out = (float*)d_out;

    const int M = in_sizes[0] / KDIM;   // 401408

    cudaFuncSetAttribute(cp2d_fp16_kernel,
                         cudaFuncAttributeMaxDynamicSharedMemorySize, SMEM_TOTAL);

    prep_wt_kernel<<<KDIM, KDIM>>>(W);
    cp2d_fp16_kernel<<<M / BM, 512, SMEM_TOTAL>>>(x, out);
}